// round 5
// baseline (speedup 1.0000x reference)
#include <cuda_runtime.h>
#include <math.h>

#define MAXN 50000
#define MAXE 800000
#define FD   256   // feature dim (both D and H)

// ---------------- scratch (static device globals; no allocation) -------------
__device__ __align__(16) float g_agg[(size_t)MAXN * FD];
__device__ __align__(16) float g_h0 [(size_t)MAXN * FD];
__device__ __align__(16) float g_h1 [(size_t)MAXN * FD];
__device__ int g_deg   [MAXN];
__device__ int g_cursor[MAXN];
__device__ int g_rowptr[MAXN + 1];
__device__ int g_col   [MAXE];
__device__ int g_is64;          // 1 if edge_index is int64, 0 if int32

// ---------------- edge-index dtype probe -------------------------------------
// int64 non-negative values < 2^31: every odd 32-bit word is 0.
// int32 data: 128 consecutive odd words all being 0 has probability ~0.
__global__ void k_detect(const int* __restrict__ ei_w) {
    int all_zero = 1;
    for (int i = 0; i < 128; i++)
        if (ei_w[2 * i + 1] != 0) { all_zero = 0; break; }
    g_is64 = all_zero;
}

__device__ __forceinline__ int load_idx(const void* ei, size_t pos, int nmax) {
    int v;
    if (g_is64) v = (int)((const long long*)ei)[pos];
    else        v = ((const int*)ei)[pos];
    // clamp: wrong dtype guess degrades to rel_err failure, not a crash
    v = min(max(v, 0), nmax - 1);
    return v;
}

// ---------------- CSR build --------------------------------------------------
__global__ void k_zero(int n) {
    int i = blockIdx.x * blockDim.x + threadIdx.x;
    if (i < n) { g_deg[i] = 0; g_cursor[i] = 0; }
}

__global__ void k_hist(const void* __restrict__ ei, int E, int Nn) {
    int e = blockIdx.x * blockDim.x + threadIdx.x;
    if (e < E) {
        int d = load_idx(ei, (size_t)E + e, Nn);   // dst row
        atomicAdd(&g_deg[d], 1);
    }
}

// Single-block exclusive scan of g_deg[0..n) -> g_rowptr[0..n]
__global__ void k_scan(int n) {
    __shared__ int ssum[1024];
    int t = threadIdx.x;
    int chunk = (n + 1023) / 1024;
    int lo = t * chunk;
    int hi = min(lo + chunk, n);
    int s = 0;
    for (int i = lo; i < hi; i++) s += g_deg[i];
    ssum[t] = s;
    __syncthreads();
    for (int off = 1; off < 1024; off <<= 1) {
        int v = (t >= off) ? ssum[t - off] : 0;
        __syncthreads();
        ssum[t] += v;
        __syncthreads();
    }
    int run = (t == 0) ? 0 : ssum[t - 1];   // exclusive prefix for this chunk
    for (int i = lo; i < hi; i++) {
        g_rowptr[i] = run;
        run += g_deg[i];
    }
    if (lo < n && hi == n) g_rowptr[n] = run;   // total
}

__global__ void k_fill(const void* __restrict__ ei, int E, int Nn) {
    int e = blockIdx.x * blockDim.x + threadIdx.x;
    if (e < E) {
        int s = load_idx(ei, (size_t)e, Nn);
        int d = load_idx(ei, (size_t)E + e, Nn);
        int pos = atomicAdd(&g_cursor[d], 1);
        g_col[g_rowptr[d] + pos] = s;
    }
}

// ---------------- aggregation: agg[i,:] = sum_{j in N(i)} x[src_j, :] --------
// one block (64 threads) per node; each thread owns 4 contiguous columns.
__global__ void k_agg(const float* __restrict__ x) {
    int node = blockIdx.x;
    int c = threadIdx.x * 4;
    float4 acc = make_float4(0.f, 0.f, 0.f, 0.f);
    int beg = g_rowptr[node];
    int end = g_rowptr[node + 1];
    for (int j = beg; j < end; j++) {
        int s = g_col[j];
        float4 v = *(const float4*)(x + (size_t)s * FD + c);
        acc.x += v.x; acc.y += v.y; acc.z += v.z; acc.w += v.w;
    }
    *(float4*)(g_agg + (size_t)node * FD + c) = acc;
}

// ---------------- fused dual-GEMM + bias + ELU -------------------------------
// out[m,n] = ELU( sum_k agg[m,k]*Wrel[k,n] + sum_k A2[m,k]*Wroot[k,n] + b[n] )
// 128x128 tile, BK=8, 256 threads, 8x8 per thread.
__global__ __launch_bounds__(256)
void k_gemm(const float* __restrict__ A2,
            const float* __restrict__ Wrel,
            const float* __restrict__ Wroot,
            const float* __restrict__ bias,
            float* __restrict__ out, int M) {
    __shared__ float As[8][128];    // transposed: As[k][m]
    __shared__ float Bs[8][128];    // Bs[k][n]

    int t  = threadIdx.x;
    int ty = t >> 4;                // 0..15 -> row group
    int tx = t & 15;                // 0..15 -> col group
    int brow = blockIdx.x * 128;
    int bcol = blockIdx.y * 128;

    float acc[8][8];
#pragma unroll
    for (int i = 0; i < 8; i++)
#pragma unroll
        for (int j = 0; j < 8; j++) acc[i][j] = 0.f;

    // A-tile load indices
    int ar = t >> 1;                // 0..127 (tile row)
    int ac = (t & 1) * 4;           // 0 or 4 (k offset within BK)
    // B-tile load indices
    int bkr = t >> 5;               // 0..7 (k row)
    int bc  = (t & 31) * 4;         // 0..124 (col)

    for (int src = 0; src < 2; src++) {
        const float* A = (src == 0) ? (const float*)g_agg : A2;
        const float* W = (src == 0) ? Wrel : Wroot;

        for (int kt = 0; kt < FD; kt += 8) {
            int grow = brow + ar;
            float4 av = (grow < M)
                ? *(const float4*)(A + (size_t)grow * FD + kt + ac)
                : make_float4(0.f, 0.f, 0.f, 0.f);
            As[ac + 0][ar] = av.x;
            As[ac + 1][ar] = av.y;
            As[ac + 2][ar] = av.z;
            As[ac + 3][ar] = av.w;

            float4 bv = *(const float4*)(W + (size_t)(kt + bkr) * FD + bcol + bc);
            *(float4*)&Bs[bkr][bc] = bv;

            __syncthreads();
#pragma unroll
            for (int k = 0; k < 8; k++) {
                float ra[8], rb[8];
#pragma unroll
                for (int i = 0; i < 8; i++) ra[i] = As[k][ty * 8 + i];
#pragma unroll
                for (int j = 0; j < 8; j++) rb[j] = Bs[k][tx * 8 + j];
#pragma unroll
                for (int i = 0; i < 8; i++)
#pragma unroll
                    for (int j = 0; j < 8; j++)
                        acc[i][j] += ra[i] * rb[j];
            }
            __syncthreads();
        }
    }

    // epilogue: + bias, ELU, store
    int cb = bcol + tx * 8;
    float bv[8];
#pragma unroll
    for (int j = 0; j < 8; j++) bv[j] = bias[cb + j];

#pragma unroll
    for (int i = 0; i < 8; i++) {
        int r = brow + ty * 8 + i;
        if (r < M) {
            float o[8];
#pragma unroll
            for (int j = 0; j < 8; j++) {
                float v = acc[i][j] + bv[j];
                o[j] = (v > 0.f) ? v : expm1f(v);
            }
            *(float4*)(out + (size_t)r * FD + cb)     = make_float4(o[0], o[1], o[2], o[3]);
            *(float4*)(out + (size_t)r * FD + cb + 4) = make_float4(o[4], o[5], o[6], o[7]);
        }
    }
}

// ---------------- launch -----------------------------------------------------
extern "C" void kernel_launch(void* const* d_in, const int* in_sizes, int n_in,
                              void* d_out, int out_size) {
    const float* x   = (const float*)d_in[0];
    const void*  ei  = d_in[1];
    const float* W1r = (const float*)d_in[2];
    const float* b1  = (const float*)d_in[3];
    const float* W1o = (const float*)d_in[4];
    const float* W2r = (const float*)d_in[5];
    const float* b2  = (const float*)d_in[6];
    const float* W2o = (const float*)d_in[7];
    const float* W3r = (const float*)d_in[8];
    const float* b3  = (const float*)d_in[9];
    const float* W3o = (const float*)d_in[10];
    float* out = (float*)d_out;

    int Nn = in_sizes[0] / FD;      // 50000
    int E  = in_sizes[1] / 2;       // 800000

    float *h0, *h1;
    cudaGetSymbolAddress((void**)&h0, g_h0);
    cudaGetSymbolAddress((void**)&h1, g_h1);

    // dtype probe + CSR build (once per launch; reused by all 3 layers)
    k_detect<<<1, 1>>>((const int*)ei);
    k_zero<<<(Nn + 255) / 256, 256>>>(Nn);
    k_hist<<<(E + 255) / 256, 256>>>(ei, E, Nn);
    k_scan<<<1, 1024>>>(Nn);
    k_fill<<<(E + 255) / 256, 256>>>(ei, E, Nn);

    dim3 gg((Nn + 127) / 128, FD / 128);

    // layer 1
    k_agg<<<Nn, 64>>>(x);
    k_gemm<<<gg, 256>>>(x, W1r, W1o, b1, h0, Nn);
    // layer 2
    k_agg<<<Nn, 64>>>(h0);
    k_gemm<<<gg, 256>>>(h0, W2r, W2o, b2, h1, Nn);
    // layer 3
    k_agg<<<Nn, 64>>>(h1);
    k_gemm<<<gg, 256>>>(h1, W3r, W3o, b3, out, Nn);
}

// round 7
// speedup vs baseline: 1.0238x; 1.0238x over previous
#include <cuda_runtime.h>
#include <math.h>

#define MAXN 50000
#define MAXE 800000
#define FD   256   // feature dim (both D and H)
typedef unsigned long long u64;

// ---------------- scratch (static device globals; no allocation) -------------
__device__ __align__(16) float g_agg[(size_t)MAXN * FD];
__device__ __align__(16) float g_h0 [(size_t)MAXN * FD];
__device__ __align__(16) float g_h1 [(size_t)MAXN * FD];
__device__ int g_deg   [MAXN];
__device__ int g_cursor[MAXN];
__device__ int g_rowptr[MAXN + 1];
__device__ int g_col   [MAXE];
__device__ int g_tmp   [MAXN];
__device__ int g_bsum  [128];
__device__ int g_is64;          // 1 if edge_index is int64, 0 if int32

// ---------------- f32x2 packed math helpers ----------------------------------
__device__ __forceinline__ void fma2(u64& d, u64 a, u64 b) {
    asm("fma.rn.f32x2 %0, %1, %2, %0;" : "+l"(d) : "l"(a), "l"(b));
}
__device__ __forceinline__ u64 pack2(float x) {
    u64 r;
    asm("mov.b64 %0, {%1, %1};" : "=l"(r) : "r"(__float_as_uint(x)));
    return r;
}

// ---------------- edge-index dtype probe -------------------------------------
__global__ void k_detect(const int* __restrict__ ei_w) {
    int all_zero = 1;
    for (int i = 0; i < 128; i++)
        if (ei_w[2 * i + 1] != 0) { all_zero = 0; break; }
    g_is64 = all_zero;
}

__device__ __forceinline__ int load_idx(const void* ei, size_t pos, int nmax) {
    int v;
    if (g_is64) v = (int)((const long long*)ei)[pos];
    else        v = ((const int*)ei)[pos];
    v = min(max(v, 0), nmax - 1);
    return v;
}

// ---------------- CSR build --------------------------------------------------
__global__ void k_zero(int n) {
    int i = blockIdx.x * blockDim.x + threadIdx.x;
    if (i < n) { g_deg[i] = 0; g_cursor[i] = 0; }
}

__global__ void k_hist(const void* __restrict__ ei, int E, int Nn) {
    int e = blockIdx.x * blockDim.x + threadIdx.x;
    if (e < E) {
        int d = load_idx(ei, (size_t)E + e, Nn);
        atomicAdd(&g_deg[d], 1);
    }
}

// 3-stage parallel exclusive scan of g_deg -> g_rowptr
#define SCAN_T 512
__global__ void k_scanA(int n) {
    __shared__ int sh[SCAN_T];
    int b = blockIdx.x, t = threadIdx.x;
    int i = b * SCAN_T + t;
    int v = (i < n) ? g_deg[i] : 0;
    sh[t] = v;
    __syncthreads();
    for (int off = 1; off < SCAN_T; off <<= 1) {
        int u = (t >= off) ? sh[t - off] : 0;
        __syncthreads();
        sh[t] += u;
        __syncthreads();
    }
    if (i < n) g_tmp[i] = sh[t];               // inclusive within block
    if (t == SCAN_T - 1) g_bsum[b] = sh[t];    // block total
}
__global__ void k_scanB(int nb) {              // 1 block, 128 threads, nb<=128
    __shared__ int sh[128];
    int t = threadIdx.x;
    sh[t] = (t < nb) ? g_bsum[t] : 0;
    __syncthreads();
    for (int off = 1; off < 128; off <<= 1) {
        int u = (t >= off) ? sh[t - off] : 0;
        __syncthreads();
        sh[t] += u;
        __syncthreads();
    }
    if (t < nb) g_bsum[t] = sh[t];             // inclusive block prefix
}
__global__ void k_scanC(int n) {
    int b = blockIdx.x, t = threadIdx.x;
    int i = b * SCAN_T + t;
    if (i < n) {
        int boff = (b == 0) ? 0 : g_bsum[b - 1];
        g_rowptr[i] = boff + g_tmp[i] - g_deg[i];          // exclusive
        if (i == n - 1) g_rowptr[n] = boff + g_tmp[i];     // total
    }
}

__global__ void k_fill(const void* __restrict__ ei, int E, int Nn) {
    int e = blockIdx.x * blockDim.x + threadIdx.x;
    if (e < E) {
        int s = load_idx(ei, (size_t)e, Nn);
        int d = load_idx(ei, (size_t)E + e, Nn);
        int pos = atomicAdd(&g_cursor[d], 1);
        g_col[g_rowptr[d] + pos] = s;
    }
}

// ---------------- aggregation: agg[i,:] = sum_{j in N(i)} x[src_j, :] --------
__global__ void k_agg(const float* __restrict__ x) {
    int node = blockIdx.x;
    int c = threadIdx.x * 4;
    float4 acc = make_float4(0.f, 0.f, 0.f, 0.f);
    int beg = g_rowptr[node];
    int end = g_rowptr[node + 1];
    for (int j = beg; j < end; j++) {
        int s = g_col[j];
        float4 v = *(const float4*)(x + (size_t)s * FD + c);
        acc.x += v.x; acc.y += v.y; acc.z += v.z; acc.w += v.w;
    }
    *(float4*)(g_agg + (size_t)node * FD + c) = acc;
}

// ---------------- fused dual-GEMM + bias + ELU (f32x2 packed, double-buffered)
// out[m,n] = ELU( agg[m,:]@Wrel + A2[m,:]@Wroot + b )[n]
// 128x128 tile, BK=8 over a flattened K=512 (two sources), 256 threads,
// 8x8 per thread held as 8x4 packed f32x2 accumulators.
__global__ __launch_bounds__(256)
void k_gemm(const float* __restrict__ Aagg,
            const float* __restrict__ A2,
            const float* __restrict__ Wrel,
            const float* __restrict__ Wroot,
            const float* __restrict__ bias,
            float* __restrict__ out, int M) {
    __shared__ float As[2][8][128];    // As[buf][k][m]
    __shared__ float Bs[2][8][128];    // Bs[buf][k][n]

    int t  = threadIdx.x;
    int ty = t >> 4;                   // 0..15
    int tx = t & 15;                   // 0..15
    int brow = blockIdx.x * 128;
    int bcol = blockIdx.y * 128;

    u64 acc2[8][4];
#pragma unroll
    for (int i = 0; i < 8; i++)
#pragma unroll
        for (int j = 0; j < 4; j++) acc2[i][j] = 0ull;  // packed (0.f, 0.f)

    int ar  = t >> 1;                  // 0..127 (tile row for A load)
    int ac  = (t & 1) * 4;             // 0 or 4
    int bkr = t >> 5;                  // 0..7
    int bc  = (t & 31) * 4;            // 0..124

    auto loadA = [&](int kt, float4& av) {
        const float* A = (kt < FD) ? Aagg : A2;
        int kk = kt & (FD - 1);
        int grow = brow + ar;
        av = (grow < M) ? *(const float4*)(A + (size_t)grow * FD + kk + ac)
                        : make_float4(0.f, 0.f, 0.f, 0.f);
    };
    auto loadB = [&](int kt, float4& bv) {
        const float* W = (kt < FD) ? Wrel : Wroot;
        int kk = kt & (FD - 1);
        bv = *(const float4*)(W + (size_t)(kk + bkr) * FD + bcol + bc);
    };
    auto stTile = [&](int b, const float4& av, const float4& bv) {
        As[b][ac + 0][ar] = av.x;
        As[b][ac + 1][ar] = av.y;
        As[b][ac + 2][ar] = av.z;
        As[b][ac + 3][ar] = av.w;
        *(float4*)&Bs[b][bkr][bc] = bv;
    };

    float4 av, bv;
    loadA(0, av); loadB(0, bv);
    stTile(0, av, bv);
    __syncthreads();

    int buf = 0;
    for (int kt = 0; kt < 2 * FD; kt += 8) {
        bool has_next = (kt + 8 < 2 * FD);
        float4 nav, nbv;
        if (has_next) { loadA(kt + 8, nav); loadB(kt + 8, nbv); }

#pragma unroll
        for (int k = 0; k < 8; k++) {
            float ra[8];
            u64 rb[4];
#pragma unroll
            for (int p = 0; p < 4; p++)
                *(float2*)&ra[2 * p] = *(const float2*)&As[buf][k][ty * 8 + 2 * p];
#pragma unroll
            for (int p = 0; p < 4; p++)
                rb[p] = *(const u64*)&Bs[buf][k][tx * 8 + 2 * p];
#pragma unroll
            for (int i = 0; i < 8; i++) {
                u64 ap = pack2(ra[i]);
#pragma unroll
                for (int jp = 0; jp < 4; jp++)
                    fma2(acc2[i][jp], ap, rb[jp]);
            }
        }

        if (has_next) stTile(buf ^ 1, nav, nbv);
        __syncthreads();
        buf ^= 1;
    }

    // epilogue: + bias, ELU, store
    int cb = bcol + tx * 8;
    float bvv[8];
#pragma unroll
    for (int j = 0; j < 8; j++) bvv[j] = bias[cb + j];

#pragma unroll
    for (int i = 0; i < 8; i++) {
        int r = brow + ty * 8 + i;
        if (r < M) {
            float o[8];
#pragma unroll
            for (int jp = 0; jp < 4; jp++) {
                u64 u = acc2[i][jp];
                float2 v = *(float2*)&u;
                float v0 = v.x + bvv[2 * jp];
                float v1 = v.y + bvv[2 * jp + 1];
                o[2 * jp]     = (v0 > 0.f) ? v0 : expm1f(v0);
                o[2 * jp + 1] = (v1 > 0.f) ? v1 : expm1f(v1);
            }
            *(float4*)(out + (size_t)r * FD + cb)     = make_float4(o[0], o[1], o[2], o[3]);
            *(float4*)(out + (size_t)r * FD + cb + 4) = make_float4(o[4], o[5], o[6], o[7]);
        }
    }
}

// ---------------- launch -----------------------------------------------------
extern "C" void kernel_launch(void* const* d_in, const int* in_sizes, int n_in,
                              void* d_out, int out_size) {
    const float* x   = (const float*)d_in[0];
    const void*  ei  = d_in[1];
    const float* W1r = (const float*)d_in[2];
    const float* b1  = (const float*)d_in[3];
    const float* W1o = (const float*)d_in[4];
    const float* W2r = (const float*)d_in[5];
    const float* b2  = (const float*)d_in[6];
    const float* W2o = (const float*)d_in[7];
    const float* W3r = (const float*)d_in[8];
    const float* b3  = (const float*)d_in[9];
    const float* W3o = (const float*)d_in[10];
    float* out = (float*)d_out;

    int Nn = in_sizes[0] / FD;      // 50000
    int E  = in_sizes[1] / 2;       // 800000

    float *agg, *h0, *h1;
    cudaGetSymbolAddress((void**)&agg, g_agg);
    cudaGetSymbolAddress((void**)&h0,  g_h0);
    cudaGetSymbolAddress((void**)&h1,  g_h1);

    // dtype probe + CSR build (once per launch; reused by all 3 layers)
    k_detect<<<1, 1>>>((const int*)ei);
    k_zero<<<(Nn + 255) / 256, 256>>>(Nn);
    k_hist<<<(E + 255) / 256, 256>>>(ei, E, Nn);
    int nsb = (Nn + SCAN_T - 1) / SCAN_T;
    k_scanA<<<nsb, SCAN_T>>>(Nn);
    k_scanB<<<1, 128>>>(nsb);
    k_scanC<<<nsb, SCAN_T>>>(Nn);
    k_fill<<<(E + 255) / 256, 256>>>(ei, E, Nn);

    dim3 gg((Nn + 127) / 128, FD / 128);

    // layer 1
    k_agg<<<Nn, 64>>>(x);
    k_gemm<<<gg, 256>>>(agg, x, W1r, W1o, b1, h0, Nn);
    // layer 2
    k_agg<<<Nn, 64>>>(h0);
    k_gemm<<<gg, 256>>>(agg, h0, W2r, W2o, b2, h1, Nn);
    // layer 3
    k_agg<<<Nn, 64>>>(h1);
    k_gemm<<<gg, 256>>>(agg, h1, W3r, W3o, b3, out, Nn);
}

// round 10
// speedup vs baseline: 1.6718x; 1.6329x over previous
#include <cuda_runtime.h>
#include <cuda_bf16.h>
#include <math.h>
#include <stdint.h>

#define MAXN 50000
#define MAXE 800000
#define FD   256
typedef unsigned long long u64;
typedef __nv_bfloat16 bf16;
typedef __nv_bfloat162 bf162;

// ---------------- scratch (static device globals; no allocation) -------------
__device__ __align__(16) float g_h0[(size_t)MAXN * FD];
__device__ __align__(16) float g_h1[(size_t)MAXN * FD];
__device__ __align__(16) bf16 g_aggh[(size_t)MAXN * FD];
__device__ __align__(16) bf16 g_aggl[(size_t)MAXN * FD];
__device__ __align__(16) bf16 g_rt0h[(size_t)MAXN * FD];
__device__ __align__(16) bf16 g_rt0l[(size_t)MAXN * FD];
__device__ __align__(16) bf16 g_rt1h[(size_t)MAXN * FD];
__device__ __align__(16) bf16 g_rt1l[(size_t)MAXN * FD];
__device__ __align__(16) bf16 g_Bth[3][512 * 256];   // W^T stacked [n=256][k=512], hi
__device__ __align__(16) bf16 g_Btl[3][512 * 256];   // lo
__device__ int g_deg   [MAXN];
__device__ int g_cursor[MAXN];
__device__ int g_rowptr[MAXN + 1];
__device__ int g_col   [MAXE];
__device__ int g_tmp   [MAXN];
__device__ int g_bsum  [128];
__device__ int g_is64;

// ---------------- PTX helpers (baseline ISA only — no 'a' features) ----------
__device__ __forceinline__ uint32_t s2u(const void* p) {
    uint32_t a;
    asm("{ .reg .u64 t; cvta.to.shared.u64 t, %1; cvt.u32.u64 %0, t; }"
        : "=r"(a) : "l"(p));
    return a;
}
__device__ __forceinline__ void ldm4(uint32_t* r, uint32_t addr) {
    asm volatile("ldmatrix.sync.aligned.m8n8.x4.shared.b16 {%0,%1,%2,%3}, [%4];"
                 : "=r"(r[0]), "=r"(r[1]), "=r"(r[2]), "=r"(r[3]) : "r"(addr));
}
__device__ __forceinline__ void mma16816(float* d, const uint32_t* a, const uint32_t* b) {
    asm volatile(
        "mma.sync.aligned.m16n8k16.row.col.f32.bf16.bf16.f32 "
        "{%0,%1,%2,%3}, {%4,%5,%6,%7}, {%8,%9}, {%0,%1,%2,%3};"
        : "+f"(d[0]), "+f"(d[1]), "+f"(d[2]), "+f"(d[3])
        : "r"(a[0]), "r"(a[1]), "r"(a[2]), "r"(a[3]), "r"(b[0]), "r"(b[1]));
}
__device__ __forceinline__ void split2(float v, bf16& h, bf16& l) {
    h = __float2bfloat16_rn(v);
    l = __float2bfloat16_rn(v - __bfloat162float(h));
}

// ---------------- edge-index dtype probe -------------------------------------
__global__ void k_detect(const int* __restrict__ ei_w) {
    int all_zero = 1;
    for (int i = 0; i < 128; i++)
        if (ei_w[2 * i + 1] != 0) { all_zero = 0; break; }
    g_is64 = all_zero;
}
__device__ __forceinline__ int load_idx(const void* ei, size_t pos, int nmax) {
    int v;
    if (g_is64) v = (int)((const long long*)ei)[pos];
    else        v = ((const int*)ei)[pos];
    return min(max(v, 0), nmax - 1);
}

// ---------------- CSR build --------------------------------------------------
__global__ void k_zero(int n) {
    int i = blockIdx.x * blockDim.x + threadIdx.x;
    if (i < n) { g_deg[i] = 0; g_cursor[i] = 0; }
}
__global__ void k_hist(const void* __restrict__ ei, int E, int Nn) {
    int e = blockIdx.x * blockDim.x + threadIdx.x;
    if (e < E) atomicAdd(&g_deg[load_idx(ei, (size_t)E + e, Nn)], 1);
}
#define SCAN_T 512
__global__ void k_scanA(int n) {
    __shared__ int sh[SCAN_T];
    int b = blockIdx.x, t = threadIdx.x;
    int i = b * SCAN_T + t;
    int v = (i < n) ? g_deg[i] : 0;
    sh[t] = v;
    __syncthreads();
    for (int off = 1; off < SCAN_T; off <<= 1) {
        int u = (t >= off) ? sh[t - off] : 0;
        __syncthreads();
        sh[t] += u;
        __syncthreads();
    }
    if (i < n) g_tmp[i] = sh[t];
    if (t == SCAN_T - 1) g_bsum[b] = sh[t];
}
__global__ void k_scanB(int nb) {
    __shared__ int sh[128];
    int t = threadIdx.x;
    sh[t] = (t < nb) ? g_bsum[t] : 0;
    __syncthreads();
    for (int off = 1; off < 128; off <<= 1) {
        int u = (t >= off) ? sh[t - off] : 0;
        __syncthreads();
        sh[t] += u;
        __syncthreads();
    }
    if (t < nb) g_bsum[t] = sh[t];
}
__global__ void k_scanC(int n) {
    int b = blockIdx.x, t = threadIdx.x;
    int i = b * SCAN_T + t;
    if (i < n) {
        int boff = (b == 0) ? 0 : g_bsum[b - 1];
        g_rowptr[i] = boff + g_tmp[i] - g_deg[i];
        if (i == n - 1) g_rowptr[n] = boff + g_tmp[i];
    }
}
__global__ void k_fill(const void* __restrict__ ei, int E, int Nn) {
    int e = blockIdx.x * blockDim.x + threadIdx.x;
    if (e < E) {
        int s = load_idx(ei, (size_t)e, Nn);
        int d = load_idx(ei, (size_t)E + e, Nn);
        int pos = atomicAdd(&g_cursor[d], 1);
        g_col[g_rowptr[d] + pos] = s;
    }
}

// ---------------- conversions ------------------------------------------------
__global__ void k_cvt(const float* __restrict__ x, bf16* __restrict__ oh,
                      bf16* __restrict__ ol, int n4) {
    int i = blockIdx.x * blockDim.x + threadIdx.x;
    if (i < n4) {
        float4 v = ((const float4*)x)[i];
        bf16 h0, l0, h1, l1, h2, l2, h3, l3;
        split2(v.x, h0, l0); split2(v.y, h1, l1);
        split2(v.z, h2, l2); split2(v.w, h3, l3);
        ((bf162*)oh)[2 * i]     = bf162{h0, h1};
        ((bf162*)oh)[2 * i + 1] = bf162{h2, h3};
        ((bf162*)ol)[2 * i]     = bf162{l0, l1};
        ((bf162*)ol)[2 * i + 1] = bf162{l2, l3};
    }
}
// weights -> transposed stacked bf16 hi/lo: Bt[n*512 + k]; k<256: Wrel, else Wroot
__global__ void k_cvtw(const float* __restrict__ Wrel, const float* __restrict__ Wroot,
                       bf16* __restrict__ oh, bf16* __restrict__ ol) {
    int idx = blockIdx.x * blockDim.x + threadIdx.x;   // 0..131071
    int n = idx >> 9, k = idx & 511;
    float w = (k < 256) ? Wrel[k * FD + n] : Wroot[(k - 256) * FD + n];
    bf16 h, l;
    split2(w, h, l);
    oh[idx] = h; ol[idx] = l;
}

// ---------------- aggregation (fp32 gather -> bf16 hi/lo out) -----------------
__global__ void k_agg(const float* __restrict__ x, bf16* __restrict__ oh,
                      bf16* __restrict__ ol) {
    int node = blockIdx.x;
    int c = threadIdx.x * 4;
    float4 acc = make_float4(0.f, 0.f, 0.f, 0.f);
    int beg = g_rowptr[node];
    int end = g_rowptr[node + 1];
    for (int j = beg; j < end; j++) {
        int s = g_col[j];
        float4 v = *(const float4*)(x + (size_t)s * FD + c);
        acc.x += v.x; acc.y += v.y; acc.z += v.z; acc.w += v.w;
    }
    bf16 h0, l0, h1, l1, h2, l2, h3, l3;
    split2(acc.x, h0, l0); split2(acc.y, h1, l1);
    split2(acc.z, h2, l2); split2(acc.w, h3, l3);
    size_t o = (size_t)node * FD + c;
    *(bf162*)(oh + o)     = bf162{h0, h1};
    *(bf162*)(oh + o + 2) = bf162{h2, h3};
    *(bf162*)(ol + o)     = bf162{l0, l1};
    *(bf162*)(ol + o + 2) = bf162{l2, l3};
}

// ---------------- HMMA dual-GEMM + bias + ELU (bf16x3 split) ------------------
// CTA: 128 rows x 128 cols (grid.y selects col half). K = 512 flattened
// (agg k<256, root k>=256), BK=32 per iteration. 8 warps in 2x4; warp = 64x32.
#define LDT 40                   // padded row stride in bf16 elems (80 B)
__global__ __launch_bounds__(256)
void k_hmma(const bf16* __restrict__ aggh, const bf16* __restrict__ aggl,
            const bf16* __restrict__ rth,  const bf16* __restrict__ rtl,
            const bf16* __restrict__ Bth,  const bf16* __restrict__ Btl,
            const float* __restrict__ bias,
            float* __restrict__ out32,
            bf16* __restrict__ orth, bf16* __restrict__ ortl, int M) {
    __shared__ bf16 sAh[128 * LDT], sAl[128 * LDT];
    __shared__ bf16 sBh[128 * LDT], sBl[128 * LDT];

    int t = threadIdx.x, lane = t & 31, wid = t >> 5;
    int wm = wid >> 2, wn = wid & 3;          // 2 x 4 warp grid
    int brow = blockIdx.x * 128;
    int bcol = blockIdx.y * 128;

    uint32_t uAh = s2u(sAh), uAl = s2u(sAl);
    uint32_t uBh = s2u(sBh), uBl = s2u(sBl);

    float acc[4][4][4];
#pragma unroll
    for (int i = 0; i < 4; i++)
#pragma unroll
        for (int j = 0; j < 4; j++)
#pragma unroll
            for (int r = 0; r < 4; r++) acc[i][j][r] = 0.f;

    // gmem->smem indices: 512 uint4 per tile, 2 per thread
    int r0 = t >> 2, c0 = t & 3;              // thread 0..255 -> (row, col16)
    int r1 = (t + 256) >> 2, c1 = (t + 256) & 3;

    for (int it = 0; it < 16; it++) {
        int kb = it * 32;
        const bf16 *Ah, *Al;
        int acol;
        if (kb < 256) { Ah = aggh; Al = aggl; acol = kb; }
        else          { Ah = rth;  Al = rtl;  acol = kb - 256; }

        int ga0 = min(brow + r0, M - 1), ga1 = min(brow + r1, M - 1);
        uint4 vh0 = *(const uint4*)(Ah + (size_t)ga0 * FD + acol + c0 * 8);
        uint4 vl0 = *(const uint4*)(Al + (size_t)ga0 * FD + acol + c0 * 8);
        uint4 vh1 = *(const uint4*)(Ah + (size_t)ga1 * FD + acol + c1 * 8);
        uint4 vl1 = *(const uint4*)(Al + (size_t)ga1 * FD + acol + c1 * 8);
        uint4 wh0 = *(const uint4*)(Bth + (size_t)(bcol + r0) * 512 + kb + c0 * 8);
        uint4 wl0 = *(const uint4*)(Btl + (size_t)(bcol + r0) * 512 + kb + c0 * 8);
        uint4 wh1 = *(const uint4*)(Bth + (size_t)(bcol + r1) * 512 + kb + c1 * 8);
        uint4 wl1 = *(const uint4*)(Btl + (size_t)(bcol + r1) * 512 + kb + c1 * 8);
        __syncthreads();      // previous iter's compute done before overwrite
        *(uint4*)(sAh + r0 * LDT + c0 * 8) = vh0;
        *(uint4*)(sAl + r0 * LDT + c0 * 8) = vl0;
        *(uint4*)(sAh + r1 * LDT + c1 * 8) = vh1;
        *(uint4*)(sAl + r1 * LDT + c1 * 8) = vl1;
        *(uint4*)(sBh + r0 * LDT + c0 * 8) = wh0;
        *(uint4*)(sBl + r0 * LDT + c0 * 8) = wl0;
        *(uint4*)(sBh + r1 * LDT + c1 * 8) = wh1;
        *(uint4*)(sBl + r1 * LDT + c1 * 8) = wl1;
        __syncthreads();

#pragma unroll
        for (int ks = 0; ks < 2; ks++) {
            // fragment smem byte offsets (ldmatrix: 16 row addrs + k-half)
            uint32_t aoff = (uint32_t)(((wm * 64 + (lane & 15)) * LDT
                                        + ks * 16 + (lane >> 4) * 8) * 2);
            uint32_t boff = (uint32_t)(((wn * 32 + (lane & 15)) * LDT
                                        + ks * 16 + (lane >> 4) * 8) * 2);
            uint32_t ah[4][4], al[4][4];
#pragma unroll
            for (int mf = 0; mf < 4; mf++) {
                ldm4(ah[mf], uAh + aoff + mf * 16 * LDT * 2);
                ldm4(al[mf], uAl + aoff + mf * 16 * LDT * 2);
            }
            uint32_t bh[4][2], bl[4][2];
#pragma unroll
            for (int np = 0; np < 2; np++) {
                uint32_t rh[4], rl[4];
                ldm4(rh, uBh + boff + np * 16 * LDT * 2);
                ldm4(rl, uBl + boff + np * 16 * LDT * 2);
                bh[2 * np][0] = rh[0]; bh[2 * np + 1][0] = rh[1];
                bh[2 * np][1] = rh[2]; bh[2 * np + 1][1] = rh[3];
                bl[2 * np][0] = rl[0]; bl[2 * np + 1][0] = rl[1];
                bl[2 * np][1] = rl[2]; bl[2 * np + 1][1] = rl[3];
            }
#pragma unroll
            for (int mf = 0; mf < 4; mf++)
#pragma unroll
                for (int nf = 0; nf < 4; nf++) {
                    mma16816(acc[mf][nf], ah[mf], bh[nf]);   // Ah*Bh
                    mma16816(acc[mf][nf], ah[mf], bl[nf]);   // Ah*Bl
                    mma16816(acc[mf][nf], al[mf], bh[nf]);   // Al*Bh
                }
        }
    }

    // epilogue: bias + ELU + fp32 store (+ bf16 hi/lo for next layer)
#pragma unroll
    for (int mf = 0; mf < 4; mf++) {
#pragma unroll
        for (int half = 0; half < 2; half++) {
            int grow = brow + wm * 64 + mf * 16 + (lane >> 2) + half * 8;
            if (grow < M) {
#pragma unroll
                for (int nf = 0; nf < 4; nf++) {
                    int gcol = bcol + wn * 32 + nf * 8 + (lane & 3) * 2;
                    float v0 = acc[mf][nf][half * 2]     + bias[gcol];
                    float v1 = acc[mf][nf][half * 2 + 1] + bias[gcol + 1];
                    v0 = (v0 > 0.f) ? v0 : expm1f(v0);
                    v1 = (v1 > 0.f) ? v1 : expm1f(v1);
                    size_t go = (size_t)grow * FD + gcol;
                    *(float2*)(out32 + go) = make_float2(v0, v1);
                    if (orth) {
                        bf16 h0, l0, h1, l1;
                        split2(v0, h0, l0); split2(v1, h1, l1);
                        *(bf162*)(orth + go) = bf162{h0, h1};
                        *(bf162*)(ortl + go) = bf162{l0, l1};
                    }
                }
            }
        }
    }
}

// ---------------- launch -----------------------------------------------------
extern "C" void kernel_launch(void* const* d_in, const int* in_sizes, int n_in,
                              void* d_out, int out_size) {
    const float* x   = (const float*)d_in[0];
    const void*  ei  = d_in[1];
    const float* W1r = (const float*)d_in[2];
    const float* b1  = (const float*)d_in[3];
    const float* W1o = (const float*)d_in[4];
    const float* W2r = (const float*)d_in[5];
    const float* b2  = (const float*)d_in[6];
    const float* W2o = (const float*)d_in[7];
    const float* W3r = (const float*)d_in[8];
    const float* b3  = (const float*)d_in[9];
    const float* W3o = (const float*)d_in[10];
    float* out = (float*)d_out;

    int Nn = in_sizes[0] / FD;      // 50000
    int E  = in_sizes[1] / 2;       // 800000

    float *h0, *h1;
    bf16 *aggh, *aggl, *rt0h, *rt0l, *rt1h, *rt1l, *Bth, *Btl;
    cudaGetSymbolAddress((void**)&h0,   g_h0);
    cudaGetSymbolAddress((void**)&h1,   g_h1);
    cudaGetSymbolAddress((void**)&aggh, g_aggh);
    cudaGetSymbolAddress((void**)&aggl, g_aggl);
    cudaGetSymbolAddress((void**)&rt0h, g_rt0h);
    cudaGetSymbolAddress((void**)&rt0l, g_rt0l);
    cudaGetSymbolAddress((void**)&rt1h, g_rt1h);
    cudaGetSymbolAddress((void**)&rt1l, g_rt1l);
    cudaGetSymbolAddress((void**)&Bth,  g_Bth);
    cudaGetSymbolAddress((void**)&Btl,  g_Btl);

    // CSR build
    k_detect<<<1, 1>>>((const int*)ei);
    k_zero<<<(Nn + 255) / 256, 256>>>(Nn);
    k_hist<<<(E + 255) / 256, 256>>>(ei, E, Nn);
    int nsb = (Nn + SCAN_T - 1) / SCAN_T;
    k_scanA<<<nsb, SCAN_T>>>(Nn);
    k_scanB<<<1, 128>>>(nsb);
    k_scanC<<<nsb, SCAN_T>>>(Nn);
    k_fill<<<(E + 255) / 256, 256>>>(ei, E, Nn);

    // weight + input conversions
    k_cvtw<<<512, 256>>>(W1r, W1o, Bth,                 Btl);
    k_cvtw<<<512, 256>>>(W2r, W2o, Bth + 512 * 256,     Btl + 512 * 256);
    k_cvtw<<<512, 256>>>(W3r, W3o, Bth + 2 * 512 * 256, Btl + 2 * 512 * 256);
    int n4 = Nn * FD / 4;
    k_cvt<<<(n4 + 255) / 256, 256>>>(x, rt0h, rt0l, n4);

    dim3 gg((Nn + 127) / 128, 2);

    // layer 1
    k_agg<<<Nn, 64>>>(x, aggh, aggl);
    k_hmma<<<gg, 256>>>(aggh, aggl, rt0h, rt0l, Bth, Btl, b1, h0, rt1h, rt1l, Nn);
    // layer 2
    k_agg<<<Nn, 64>>>(h0, aggh, aggl);
    k_hmma<<<gg, 256>>>(aggh, aggl, rt1h, rt1l, Bth + 512 * 256, Btl + 512 * 256,
                        b2, h1, rt0h, rt0l, Nn);
    // layer 3 -> final fp32 output only
    k_agg<<<Nn, 64>>>(h1, aggh, aggl);
    k_hmma<<<gg, 256>>>(aggh, aggl, rt0h, rt0l,
                        Bth + 2 * 512 * 256, Btl + 2 * 512 * 256,
                        b3, out, (bf16*)nullptr, (bf16*)nullptr, Nn);
}